// round 13
// baseline (speedup 1.0000x reference)
#include <cuda_runtime.h>
#include <cuda_fp16.h>
#include <math.h>
#include <stdint.h>

#define Bd 8
#define Td 2048
#define Sd 7
#define Hd 512
#define K2 1024                 // GEMM K
#define MROWS (Bd*Td*Sd)        // 114688

#define MT 64                   // CTA M tile
#define NTILE 512               // CTA N tile (full N)
#define NCHUNK 16               // K=64 per period
#define NTHREADS 256

// smem per stage (bytes): A 64x64 fp16 (8KB) + B 512x64 fp16 (64KB)
#define OFF_A 0
#define OFF_B 8192
#define STG   73728
#define GEMM_SMEM (2*STG)       // 147456

// ---------------------------------------------------------------------------
// Device scratch (no cudaMalloc allowed)
// ---------------------------------------------------------------------------
__device__ __half2 g_msg[(size_t)MROWS * Hd / 2]; // GEMM output (pre bias/relu), fp16
__device__ unsigned short g_bh[Hd * K2];          // Wm^T fp16 [N=512][K=1024]
__device__ int g_idx[Bd * Td];

// ---------------------------------------------------------------------------
// PTX helpers (plain sm_80+ features only — target is compute_103, no 'a')
// ---------------------------------------------------------------------------
__device__ __forceinline__ uint32_t smem_u32(const void* p) {
    uint32_t a;
    asm("{ .reg .u64 t; cvta.to.shared.u64 t, %1; cvt.u32.u64 %0, t; }" : "=r"(a) : "l"(p));
    return a;
}
__device__ __forceinline__ uint32_t sw128(uint32_t off) { return off ^ ((off >> 3) & 0x70); }

#define LDSM4(r, addr) \
    asm volatile("ldmatrix.sync.aligned.m8n8.x4.shared.b16 {%0,%1,%2,%3}, [%4];" \
        : "=r"((r)[0]), "=r"((r)[1]), "=r"((r)[2]), "=r"((r)[3]) : "r"(addr))

#define MMA(c, a, b) \
    asm volatile("mma.sync.aligned.m16n8k16.row.col.f32.f16.f16.f32 " \
        "{%0,%1,%2,%3}, {%4,%5,%6,%7}, {%8,%9}, {%0,%1,%2,%3};" \
        : "+f"((c)[0]), "+f"((c)[1]), "+f"((c)[2]), "+f"((c)[3]) \
        : "r"((a)[0]), "r"((a)[1]), "r"((a)[2]), "r"((a)[3]), "r"((b)[0]), "r"((b)[1]))

#define CP16(dst, src) \
    asm volatile("cp.async.cg.shared.global [%0], [%1], 16;" :: "r"(dst), "l"(src) : "memory")
#define CP_COMMIT() asm volatile("cp.async.commit_group;" ::: "memory")
#define CP_WAIT0()  asm volatile("cp.async.wait_group 0;" ::: "memory")

// ---------------------------------------------------------------------------
// Prep: Wm fp32 -> transposed fp16 [512][1024]  (blocks 0..511)
//       + backward min-scan of u (blocks 512..519)
// ---------------------------------------------------------------------------
__global__ void prep_kernel(const float* __restrict__ Wm, const int* __restrict__ u)
{
    if (blockIdx.x < Hd) {
        const int n = blockIdx.x;
        for (int k = threadIdx.x; k < K2; k += blockDim.x) {
            const float x = Wm[(size_t)k * Hd + n];
            g_bh[n * K2 + k] = __half_as_ushort(__float2half_rn(x));
        }
        return;
    }
    __shared__ int sv[Td];
    const int b = blockIdx.x - Hd;
    for (int t = threadIdx.x; t < Td; t += blockDim.x)
        sv[t] = (u[(size_t)b * Td + t] > 0) ? t : Td;
    __syncthreads();
    for (int off = 1; off < Td; off <<= 1) {
        int tmp[Td / 256];
        #pragma unroll
        for (int i = 0; i < Td / 256; ++i) {
            const int t = threadIdx.x + i * 256;
            int v = sv[t];
            if (t + off < Td) v = min(v, sv[t + off]);
            tmp[i] = v;
        }
        __syncthreads();
        #pragma unroll
        for (int i = 0; i < Td / 256; ++i)
            sv[threadIdx.x + i * 256] = tmp[i];
        __syncthreads();
    }
    for (int t = threadIdx.x; t < Td; t += blockDim.x) {
        const int n = sv[t];
        g_idx[(size_t)b * Td + t] = (n < Td) ? n : t;
    }
}

// ---------------------------------------------------------------------------
// GEMM building blocks (kc = 64-wide K chunk index, 0..15)
// ---------------------------------------------------------------------------
__device__ __forceinline__ void load_a_regs(const float* __restrict__ senders,
                                            size_t m0, int kc, int tid, float4 (&va)[4])
{
    #pragma unroll
    for (int j = 0; j < 4; ++j) {
        const int i = tid + j * NTHREADS;      // 0..1023
        const int row = i >> 4, c = i & 15;    // row 0..63
        va[j] = ((const float4*)(senders + (m0 + row) * K2 + kc * 64))[c];
    }
}

__device__ __forceinline__ void cp_b_chunk(uint32_t dstStage, int kc, int tid)
{
    #pragma unroll
    for (int j = 0; j < 16; ++j) {
        const int i = tid + j * NTHREADS;      // 0..4095
        const int row = i >> 3, u = i & 7;     // row 0..511
        const char* gh = (const char*)(g_bh + (size_t)row * K2 + kc * 64) + u * 16;
        const uint32_t swo = sw128(row * 128 + u * 16);
        CP16(dstStage + OFF_B + swo, gh);
    }
    CP_COMMIT();
}

__device__ __forceinline__ void convert_store_a(const float4 (&va)[4], char* dstStage, int tid)
{
    #pragma unroll
    for (int j = 0; j < 4; ++j) {
        const int i = tid + j * NTHREADS;
        const int row = i >> 4, c = i & 15;
        const float4 v = va[j];
        uint32_t p0, p1;
        asm("cvt.rn.f16x2.f32 %0, %1, %2;" : "=r"(p0) : "f"(v.y), "f"(v.x));
        asm("cvt.rn.f16x2.f32 %0, %1, %2;" : "=r"(p1) : "f"(v.w), "f"(v.z));
        const uint32_t swo = sw128(row * 128 + c * 8);
        *(uint2*)(dstStage + OFF_A + swo) = make_uint2(p0, p1);
    }
}

// warp tile 32(M) x 128(N): wm in {0,1}, wn in {0..3}
__device__ __forceinline__ void compute_k16(uint32_t sg, int kk, int lane, int wm, int wn,
                                            float (&acc)[2][16][4])
{
    uint32_t af[2][4], bf[8][4];
    const int koffA = kk * 32 + ((lane >> 4) << 4);
    const int arow = wm * 32 + (lane & 15);
    #pragma unroll
    for (int mt = 0; mt < 2; ++mt)
        LDSM4(af[mt], sg + OFF_A + sw128((arow + mt * 16) * 128 + koffA));
    const int nrow = wn * 128 + (lane & 7) + ((lane & 16) ? 8 : 0);
    const int koffB = kk * 32 + ((lane >> 3) & 1) * 16;
    #pragma unroll
    for (int h = 0; h < 8; ++h)
        LDSM4(bf[h], sg + OFF_B + sw128((nrow + h * 16) * 128 + koffB));

    #pragma unroll
    for (int mt = 0; mt < 2; ++mt)
        #pragma unroll
        for (int nt = 0; nt < 16; ++nt)
            MMA(acc[mt][nt], af[mt], (&bf[nt >> 1][(nt & 1) * 2]));
}

// ---------------------------------------------------------------------------
// fp16 GEMM via mma.sync (fp32 accum): g_msg = fp16(senders @ Wm)
// gridDim = 1792 m-tiles (full N per CTA); 256 thr; warp grid 2(M)x4(N), 32x128
// 2-stage double buffer, K=64 per period.
// ---------------------------------------------------------------------------
__global__ void __launch_bounds__(NTHREADS, 1)
gemm_kernel(const float* __restrict__ senders)
{
    extern __shared__ __align__(128) char smem[];
    const uint32_t sb = smem_u32(smem);
    const int tid = threadIdx.x, lane = tid & 31, wid = tid >> 5;
    const int wm = wid >> 2, wn = wid & 3;
    const size_t m0 = (size_t)blockIdx.x * MT;

    float acc[2][16][4];
    #pragma unroll
    for (int i = 0; i < 2; ++i)
        #pragma unroll
        for (int j = 0; j < 16; ++j)
            #pragma unroll
            for (int q = 0; q < 4; ++q) acc[i][j][q] = 0.f;

    float4 va[4];

    // ---- prologue: fill stage 0 ----
    {
        load_a_regs(senders, m0, 0, tid, va);
        cp_b_chunk(sb, 0, tid);
        convert_store_a(va, smem, tid);
        CP_WAIT0();
        __syncthreads();
    }

    // ---- main loop: conversion pipelined between compute halves ----
    for (int kc = 0; kc < NCHUNK; ++kc) {
        const int st = kc & 1;
        const uint32_t sg = sb + st * STG;
        char* nxt = smem + (st ^ 1) * STG;
        const uint32_t nxtu = sb + (st ^ 1) * STG;
        const bool more = (kc + 1 < NCHUNK);

        if (more) {
            load_a_regs(senders, m0, kc + 1, tid, va);   // LDG in flight
            cp_b_chunk(nxtu, kc + 1, tid);               // B async in flight
        }

        compute_k16(sg, 0, lane, wm, wn, acc);
        compute_k16(sg, 1, lane, wm, wn, acc);

        if (more) convert_store_a(va, nxt, tid);         // hidden under tensor drain

        compute_k16(sg, 2, lane, wm, wn, acc);
        compute_k16(sg, 3, lane, wm, wn, acc);

        if (more) CP_WAIT0();
        __syncthreads();
    }

    // ---- epilogue: write fp16 GEMM result ----
    const int g = lane >> 2, tg = lane & 3;
    #pragma unroll
    for (int mt = 0; mt < 2; ++mt) {
        #pragma unroll
        for (int nt = 0; nt < 16; ++nt) {
            const size_t row = m0 + wm * 32 + mt * 16 + g;
            const int col = wn * 128 + nt * 8 + tg * 2;
            __half2* p = g_msg + (row * Hd + col) / 2;
            p[0]          = __floats2half2_rn(acc[mt][nt][0], acc[mt][nt][1]);
            p[8 * Hd / 2] = __floats2half2_rn(acc[mt][nt][2], acc[mt][nt][3]);
        }
    }
}

// ---------------------------------------------------------------------------
// Attention + hx gather: per (b,t) -> bias+relu+mask, masked softmax over S=7,
// aggregate; also copies hx_s[b, idx[bt]] into out[..., H:2H].
// ---------------------------------------------------------------------------
__global__ void __launch_bounds__(128)
attn_kernel(const float* __restrict__ query,
            const float* __restrict__ smask,
            const float* __restrict__ bm,
            const float* __restrict__ hx,
            float* __restrict__ out)
{
    __shared__ float red[4][Sd];
    __shared__ float s_att[Sd];
    const int bt = blockIdx.x;
    const int tid = threadIdx.x;
    const int lane = tid & 31, wid = tid >> 5;

    // ---- hx gather half (independent of attention math) ----
    {
        const int b = bt >> 11;                         // T = 2048
        const int idx = g_idx[bt];
        const float4 v = ((const float4*)(hx + ((size_t)(b * Td + idx)) * Hd))[tid];
        ((float4*)(out + (size_t)bt * (2 * Hd) + Hd))[tid] = v;
    }

    const float4 q   = ((const float4*)(query + (size_t)bt * Hd))[tid];
    const float4 bmv = ((const float4*)bm)[tid];
    float msk[Sd];
    #pragma unroll
    for (int s = 0; s < Sd; ++s) msk[s] = smask[(size_t)bt * Sd + s];

    float4 m[Sd];
    float lg[Sd];
    #pragma unroll
    for (int s = 0; s < Sd; ++s) {
        const uint2 raw = *(const uint2*)(g_msg + ((size_t)bt * Sd + s) * Hd / 2 + tid * 2);
        const float2 f0 = __half22float2(*(const __half2*)&raw.x);
        const float2 f1 = __half22float2(*(const __half2*)&raw.y);
        float4 mv;
        mv.x = fmaxf(f0.x + bmv.x, 0.f) * msk[s];
        mv.y = fmaxf(f0.y + bmv.y, 0.f) * msk[s];
        mv.z = fmaxf(f1.x + bmv.z, 0.f) * msk[s];
        mv.w = fmaxf(f1.y + bmv.w, 0.f) * msk[s];
        m[s] = mv;
        float v = q.x * mv.x + q.y * mv.y + q.z * mv.z + q.w * mv.w;
        v += __shfl_xor_sync(0xffffffffu, v, 16);
        v += __shfl_xor_sync(0xffffffffu, v, 8);
        v += __shfl_xor_sync(0xffffffffu, v, 4);
        v += __shfl_xor_sync(0xffffffffu, v, 2);
        v += __shfl_xor_sync(0xffffffffu, v, 1);
        lg[s] = v;
    }
    if (lane == 0) {
        #pragma unroll
        for (int s = 0; s < Sd; ++s) red[wid][s] = lg[s];
    }
    __syncthreads();
    if (tid == 0) {
        float l[Sd], maxv = -3.0e38f;
        int any = 0;
        #pragma unroll
        for (int s = 0; s < Sd; ++s) {
            l[s] = (red[0][s] + red[1][s] + red[2][s] + red[3][s]) * 0.044194173824159216f;
            if (msk[s] > 0.f) { any = 1; if (l[s] > maxv) maxv = l[s]; }
        }
        float sum = 0.f, e[Sd];
        #pragma unroll
        for (int s = 0; s < Sd; ++s) {
            e[s] = (msk[s] > 0.f) ? expf(l[s] - maxv) : 0.f;
            sum += e[s];
        }
        const float inv = (any && sum > 0.f) ? (1.f / sum) : 0.f;
        #pragma unroll
        for (int s = 0; s < Sd; ++s) s_att[s] = e[s] * inv;
    }
    __syncthreads();

    float4 a = make_float4(0.f, 0.f, 0.f, 0.f);
    #pragma unroll
    for (int s = 0; s < Sd; ++s) {
        const float w = s_att[s];
        a.x = fmaf(w, m[s].x, a.x);
        a.y = fmaf(w, m[s].y, a.y);
        a.z = fmaf(w, m[s].z, a.z);
        a.w = fmaf(w, m[s].w, a.w);
    }
    ((float4*)(out + (size_t)bt * (2 * Hd)))[tid] = a;
}

// ---------------------------------------------------------------------------
extern "C" void kernel_launch(void* const* d_in, const int* in_sizes, int n_in,
                              void* d_out, int out_size)
{
    const float* query   = (const float*)d_in[0];
    const float* senders = (const float*)d_in[1];
    const float* smaskp  = (const float*)d_in[2];
    const float* Wm      = (const float*)d_in[3];
    const float* bm      = (const float*)d_in[4];
    const float* hx      = (const float*)d_in[5];
    const int*   u       = (const int*)d_in[6];
    float* out = (float*)d_out;

    cudaFuncSetAttribute(gemm_kernel,
                         cudaFuncAttributeMaxDynamicSharedMemorySize, GEMM_SMEM);

    prep_kernel<<<Hd + Bd, 256>>>(Wm, u);
    gemm_kernel<<<MROWS / MT, NTHREADS, GEMM_SMEM>>>(senders);
    attn_kernel<<<Bd * Td, 128>>>(query, smaskp, bm, hx, out);
}

// round 14
// speedup vs baseline: 1.0106x; 1.0106x over previous
#include <cuda_runtime.h>
#include <cuda_fp16.h>
#include <math.h>
#include <stdint.h>

#define Bd 8
#define Td 2048
#define Sd 7
#define Hd 512
#define K2 1024                 // GEMM K
#define MROWS (Bd*Td*Sd)        // 114688

#define MT 128                  // CTA M tile
#define NTILE 256               // CTA N tile
#define NCHUNK2 8               // K=128 per barrier period
#define NTHREADS 256

// smem stage layout (bytes): two 64-wide sub-tiles each for A and B
#define OFF_A0 0
#define OFF_A1 16384
#define OFF_B0 32768
#define OFF_B1 65536
#define STG    98304
#define GEMM_SMEM (2*STG)       // 196608

// ---------------------------------------------------------------------------
// Device scratch (no cudaMalloc allowed)
// ---------------------------------------------------------------------------
__device__ __half2 g_msg[(size_t)MROWS * Hd / 2]; // GEMM output (pre bias/relu), fp16
__device__ unsigned short g_bh[Hd * K2];          // Wm^T fp16 [N=512][K=1024]
__device__ int g_idx[Bd * Td];

// ---------------------------------------------------------------------------
// PTX helpers (plain sm_80+ features only — target is compute_103, no 'a')
// ---------------------------------------------------------------------------
__device__ __forceinline__ uint32_t smem_u32(const void* p) {
    uint32_t a;
    asm("{ .reg .u64 t; cvta.to.shared.u64 t, %1; cvt.u32.u64 %0, t; }" : "=r"(a) : "l"(p));
    return a;
}
__device__ __forceinline__ uint32_t sw128(uint32_t off) { return off ^ ((off >> 3) & 0x70); }

#define LDSM4(r, addr) \
    asm volatile("ldmatrix.sync.aligned.m8n8.x4.shared.b16 {%0,%1,%2,%3}, [%4];" \
        : "=r"((r)[0]), "=r"((r)[1]), "=r"((r)[2]), "=r"((r)[3]) : "r"(addr))

#define MMA(c, a, b) \
    asm volatile("mma.sync.aligned.m16n8k16.row.col.f32.f16.f16.f32 " \
        "{%0,%1,%2,%3}, {%4,%5,%6,%7}, {%8,%9}, {%0,%1,%2,%3};" \
        : "+f"((c)[0]), "+f"((c)[1]), "+f"((c)[2]), "+f"((c)[3]) \
        : "r"((a)[0]), "r"((a)[1]), "r"((a)[2]), "r"((a)[3]), "r"((b)[0]), "r"((b)[1]))

#define CP16(dst, src) \
    asm volatile("cp.async.cg.shared.global [%0], [%1], 16;" :: "r"(dst), "l"(src) : "memory")
#define CP_COMMIT() asm volatile("cp.async.commit_group;" ::: "memory")
#define CP_WAIT0()  asm volatile("cp.async.wait_group 0;" ::: "memory")

// ---------------------------------------------------------------------------
// Prep: Wm fp32 -> transposed fp16 [512][1024]  (blocks 0..511)
//       + backward min-scan of u (blocks 512..519)
// ---------------------------------------------------------------------------
__global__ void prep_kernel(const float* __restrict__ Wm, const int* __restrict__ u)
{
    if (blockIdx.x < Hd) {
        const int n = blockIdx.x;
        for (int k = threadIdx.x; k < K2; k += blockDim.x) {
            const float x = Wm[(size_t)k * Hd + n];
            g_bh[n * K2 + k] = __half_as_ushort(__float2half_rn(x));
        }
        return;
    }
    __shared__ int sv[Td];
    const int b = blockIdx.x - Hd;
    for (int t = threadIdx.x; t < Td; t += blockDim.x)
        sv[t] = (u[(size_t)b * Td + t] > 0) ? t : Td;
    __syncthreads();
    for (int off = 1; off < Td; off <<= 1) {
        int tmp[Td / 256];
        #pragma unroll
        for (int i = 0; i < Td / 256; ++i) {
            const int t = threadIdx.x + i * 256;
            int v = sv[t];
            if (t + off < Td) v = min(v, sv[t + off]);
            tmp[i] = v;
        }
        __syncthreads();
        #pragma unroll
        for (int i = 0; i < Td / 256; ++i)
            sv[threadIdx.x + i * 256] = tmp[i];
        __syncthreads();
    }
    for (int t = threadIdx.x; t < Td; t += blockDim.x) {
        const int n = sv[t];
        g_idx[(size_t)b * Td + t] = (n < Td) ? n : t;
    }
}

// ---------------------------------------------------------------------------
// GEMM building blocks (kc64 = 64-wide K sub-chunk index, 0..15)
// ---------------------------------------------------------------------------
__device__ __forceinline__ void load_a_regs(const float* __restrict__ senders,
                                            size_t m0, int kc64, int tid, float4 (&va)[8])
{
    #pragma unroll
    for (int j = 0; j < 8; ++j) {
        const int i = tid + j * NTHREADS;
        const int row = i >> 4, c = i & 15;
        va[j] = ((const float4*)(senders + (m0 + row) * K2 + kc64 * 64))[c];
    }
}

__device__ __forceinline__ void cp_b_sub(uint32_t dstSub, int n0, int kc64, int tid)
{
    #pragma unroll
    for (int j = 0; j < 8; ++j) {
        const int i = tid + j * NTHREADS;      // 0..2047
        const int row = i >> 3, u = i & 7;     // row 0..255
        const char* gh = (const char*)(g_bh + (size_t)(n0 + row) * K2 + kc64 * 64) + u * 16;
        const uint32_t swo = sw128(row * 128 + u * 16);
        CP16(dstSub + swo, gh);
    }
}

__device__ __forceinline__ void convert_store_a(const float4 (&va)[8], char* dstSub, int tid)
{
    #pragma unroll
    for (int j = 0; j < 8; ++j) {
        const int i = tid + j * NTHREADS;
        const int row = i >> 4, c = i & 15;
        const float4 v = va[j];
        uint32_t p0, p1;
        asm("cvt.rn.f16x2.f32 %0, %1, %2;" : "=r"(p0) : "f"(v.y), "f"(v.x));
        asm("cvt.rn.f16x2.f32 %0, %1, %2;" : "=r"(p1) : "f"(v.w), "f"(v.z));
        const uint32_t swo = sw128(row * 128 + c * 8);
        *(uint2*)(dstSub + swo) = make_uint2(p0, p1);
    }
}

__device__ __forceinline__ void compute_k16(uint32_t aBase, uint32_t bBase, int kk,
                                            int lane, int wm, int wn, float (&acc)[4][8][4])
{
    uint32_t af[4][4], bf[4][4];
    const int koffA = kk * 32 + ((lane >> 4) << 4);
    const int arow = wm * 64 + (lane & 15);
    #pragma unroll
    for (int mt = 0; mt < 4; ++mt)
        LDSM4(af[mt], aBase + sw128((arow + mt * 16) * 128 + koffA));
    const int nrow = wn * 64 + (lane & 7) + ((lane & 16) ? 8 : 0);
    const int koffB = kk * 32 + ((lane >> 3) & 1) * 16;
    #pragma unroll
    for (int h = 0; h < 4; ++h)
        LDSM4(bf[h], bBase + sw128((nrow + h * 16) * 128 + koffB));

    #pragma unroll
    for (int mt = 0; mt < 4; ++mt)
        #pragma unroll
        for (int nt = 0; nt < 8; ++nt)
            MMA(acc[mt][nt], af[mt], (&bf[nt >> 1][(nt & 1) * 2]));
}

// ---------------------------------------------------------------------------
// fp16 GEMM via mma.sync (fp32 accum): g_msg = fp16(senders @ Wm)
// gridDim = (2 n-tiles, 896 m-tiles); 256 thr; warp grid 2(M)x4(N), 64x64 each
// K=128 per barrier period (two 64-wide sub-tiles), 2-stage double buffer.
// ---------------------------------------------------------------------------
__global__ void __launch_bounds__(NTHREADS, 1)
gemm_kernel(const float* __restrict__ senders)
{
    extern __shared__ __align__(128) char smem[];
    const uint32_t sb = smem_u32(smem);
    const int tid = threadIdx.x, lane = tid & 31, wid = tid >> 5;
    const int wm = wid >> 2, wn = wid & 3;
    const int n0 = blockIdx.x * NTILE;
    const size_t m0 = (size_t)blockIdx.y * MT;

    float acc[4][8][4];
    #pragma unroll
    for (int i = 0; i < 4; ++i)
        #pragma unroll
        for (int j = 0; j < 8; ++j)
            #pragma unroll
            for (int q = 0; q < 4; ++q) acc[i][j][q] = 0.f;

    float4 va[8];

    // ---- prologue: fill stage 0 (both sub-tiles) ----
    {
        cp_b_sub(sb + OFF_B0, n0, 0, tid);
        cp_b_sub(sb + OFF_B1, n0, 1, tid);
        CP_COMMIT();
        load_a_regs(senders, m0, 0, tid, va);
        convert_store_a(va, smem + OFF_A0, tid);
        load_a_regs(senders, m0, 1, tid, va);
        convert_store_a(va, smem + OFF_A1, tid);
        CP_WAIT0();
        __syncthreads();
    }

    // ---- main loop: one barrier period per K=128 ----
    for (int kc2 = 0; kc2 < NCHUNK2; ++kc2) {
        const int st = kc2 & 1;
        const uint32_t sg = sb + st * STG;
        char* nxt = smem + (st ^ 1) * STG;
        const uint32_t nxtu = sb + (st ^ 1) * STG;
        const bool more = (kc2 + 1 < NCHUNK2);

        if (more) {
            cp_b_sub(nxtu + OFF_B0, n0, 2 * kc2 + 2, tid);
            cp_b_sub(nxtu + OFF_B1, n0, 2 * kc2 + 3, tid);
            CP_COMMIT();
            load_a_regs(senders, m0, 2 * kc2 + 2, tid, va);  // half0 LDG in flight
        }

        compute_k16(sg + OFF_A0, sg + OFF_B0, 0, lane, wm, wn, acc);
        compute_k16(sg + OFF_A0, sg + OFF_B0, 1, lane, wm, wn, acc);

        if (more) convert_store_a(va, nxt + OFF_A0, tid);

        compute_k16(sg + OFF_A0, sg + OFF_B0, 2, lane, wm, wn, acc);
        compute_k16(sg + OFF_A0, sg + OFF_B0, 3, lane, wm, wn, acc);

        if (more) load_a_regs(senders, m0, 2 * kc2 + 3, tid, va);  // half1 LDG in flight

        compute_k16(sg + OFF_A1, sg + OFF_B1, 0, lane, wm, wn, acc);
        compute_k16(sg + OFF_A1, sg + OFF_B1, 1, lane, wm, wn, acc);

        if (more) convert_store_a(va, nxt + OFF_A1, tid);

        compute_k16(sg + OFF_A1, sg + OFF_B1, 2, lane, wm, wn, acc);
        compute_k16(sg + OFF_A1, sg + OFF_B1, 3, lane, wm, wn, acc);

        if (more) CP_WAIT0();
        __syncthreads();
    }

    // ---- epilogue: write fp16 GEMM result ----
    const int g = lane >> 2, tg = lane & 3;
    #pragma unroll
    for (int mt = 0; mt < 4; ++mt) {
        #pragma unroll
        for (int nt = 0; nt < 8; ++nt) {
            const size_t row = m0 + wm * 64 + mt * 16 + g;
            const int col = n0 + wn * 64 + nt * 8 + tg * 2;
            __half2* p = g_msg + (row * Hd + col) / 2;
            p[0]          = __floats2half2_rn(acc[mt][nt][0], acc[mt][nt][1]);
            p[8 * Hd / 2] = __floats2half2_rn(acc[mt][nt][2], acc[mt][nt][3]);
        }
    }
}

// ---------------------------------------------------------------------------
// Attention + hx gather: 2 (b,t) per 256-thread CTA. Per half-block:
// bias+relu+mask, masked softmax over S=7, aggregate; hx gather into out.
// ---------------------------------------------------------------------------
__global__ void __launch_bounds__(256)
attn_kernel(const float* __restrict__ query,
            const float* __restrict__ smask,
            const float* __restrict__ bm,
            const float* __restrict__ hx,
            float* __restrict__ out)
{
    __shared__ float red[8][Sd];
    __shared__ float s_att[2][Sd];
    const int half = threadIdx.x >> 7;               // 0 or 1
    const int tid  = threadIdx.x & 127;              // within half-block
    const int bt   = blockIdx.x * 2 + half;
    const int lane = threadIdx.x & 31;
    const int wid  = threadIdx.x >> 5;               // 0..7

    // ---- hx gather half (independent of attention math) ----
    {
        const int b = bt >> 11;                      // T = 2048
        const int idx = g_idx[bt];
        const float4 v = ((const float4*)(hx + ((size_t)(b * Td + idx)) * Hd))[tid];
        ((float4*)(out + (size_t)bt * (2 * Hd) + Hd))[tid] = v;
    }

    const float4 q   = ((const float4*)(query + (size_t)bt * Hd))[tid];
    const float4 bmv = ((const float4*)bm)[tid];
    float msk[Sd];
    #pragma unroll
    for (int s = 0; s < Sd; ++s) msk[s] = smask[(size_t)bt * Sd + s];

    float4 m[Sd];
    float lg[Sd];
    #pragma unroll
    for (int s = 0; s < Sd; ++s) {
        const uint2 raw = *(const uint2*)(g_msg + ((size_t)bt * Sd + s) * Hd / 2 + tid * 2);
        const float2 f0 = __half22float2(*(const __half2*)&raw.x);
        const float2 f1 = __half22float2(*(const __half2*)&raw.y);
        float4 mv;
        mv.x = fmaxf(f0.x + bmv.x, 0.f) * msk[s];
        mv.y = fmaxf(f0.y + bmv.y, 0.f) * msk[s];
        mv.z = fmaxf(f1.x + bmv.z, 0.f) * msk[s];
        mv.w = fmaxf(f1.y + bmv.w, 0.f) * msk[s];
        m[s] = mv;
        float v = q.x * mv.x + q.y * mv.y + q.z * mv.z + q.w * mv.w;
        v += __shfl_xor_sync(0xffffffffu, v, 16);
        v += __shfl_xor_sync(0xffffffffu, v, 8);
        v += __shfl_xor_sync(0xffffffffu, v, 4);
        v += __shfl_xor_sync(0xffffffffu, v, 2);
        v += __shfl_xor_sync(0xffffffffu, v, 1);
        lg[s] = v;
    }
    if (lane == 0) {
        #pragma unroll
        for (int s = 0; s < Sd; ++s) red[wid][s] = lg[s];
    }
    __syncthreads();
    if (tid == 0) {
        const int rb = half * 4;
        float l[Sd], maxv = -3.0e38f;
        int any = 0;
        #pragma unroll
        for (int s = 0; s < Sd; ++s) {
            l[s] = (red[rb][s] + red[rb + 1][s] + red[rb + 2][s] + red[rb + 3][s])
                 * 0.044194173824159216f;
            if (msk[s] > 0.f) { any = 1; if (l[s] > maxv) maxv = l[s]; }
        }
        float sum = 0.f, e[Sd];
        #pragma unroll
        for (int s = 0; s < Sd; ++s) {
            e[s] = (msk[s] > 0.f) ? expf(l[s] - maxv) : 0.f;
            sum += e[s];
        }
        const float inv = (any && sum > 0.f) ? (1.f / sum) : 0.f;
        #pragma unroll
        for (int s = 0; s < Sd; ++s) s_att[half][s] = e[s] * inv;
    }
    __syncthreads();

    float4 a = make_float4(0.f, 0.f, 0.f, 0.f);
    #pragma unroll
    for (int s = 0; s < Sd; ++s) {
        const float w = s_att[half][s];
        a.x = fmaf(w, m[s].x, a.x);
        a.y = fmaf(w, m[s].y, a.y);
        a.z = fmaf(w, m[s].z, a.z);
        a.w = fmaf(w, m[s].w, a.w);
    }
    ((float4*)(out + (size_t)bt * (2 * Hd)))[tid] = a;
}

// ---------------------------------------------------------------------------
extern "C" void kernel_launch(void* const* d_in, const int* in_sizes, int n_in,
                              void* d_out, int out_size)
{
    const float* query   = (const float*)d_in[0];
    const float* senders = (const float*)d_in[1];
    const float* smaskp  = (const float*)d_in[2];
    const float* Wm      = (const float*)d_in[3];
    const float* bm      = (const float*)d_in[4];
    const float* hx      = (const float*)d_in[5];
    const int*   u       = (const int*)d_in[6];
    float* out = (float*)d_out;

    cudaFuncSetAttribute(gemm_kernel,
                         cudaFuncAttributeMaxDynamicSharedMemorySize, GEMM_SMEM);

    prep_kernel<<<Hd + Bd, 256>>>(Wm, u);
    gemm_kernel<<<dim3(2, MROWS / MT), NTHREADS, GEMM_SMEM>>>(senders);
    attn_kernel<<<Bd * Td / 2, 256>>>(query, smaskp, bm, hx, out);
}

// round 15
// speedup vs baseline: 1.0429x; 1.0320x over previous
#include <cuda_runtime.h>
#include <cuda_fp16.h>
#include <math.h>
#include <stdint.h>

#define Bd 8
#define Td 2048
#define Sd 7
#define Hd 512
#define K2 1024                 // GEMM K
#define MROWS (Bd*Td*Sd)        // 114688

#define MT 128                  // CTA M tile
#define NTILE 256               // CTA N tile
#define NCHUNK2 8               // K=128 per barrier period
#define NTHREADS 256

// smem stage layout (bytes): two 64-wide sub-tiles each for A and B
#define OFF_A0 0
#define OFF_A1 16384
#define OFF_B0 32768
#define OFF_B1 65536
#define STG    98304
#define GEMM_SMEM (2*STG)       // 196608

// prep transpose tiling: 32x32 fp32->fp16 tiles
#define TP_BLKS ((Hd/32)*(K2/32))   // 16*32 = 512

// ---------------------------------------------------------------------------
// Device scratch (no cudaMalloc allowed)
// ---------------------------------------------------------------------------
__device__ __half2 g_msg[(size_t)MROWS * Hd / 2]; // GEMM output (pre bias/relu), fp16
__device__ unsigned short g_bh[Hd * K2];          // Wm^T fp16 [N=512][K=1024]
__device__ int g_idx[Bd * Td];

// ---------------------------------------------------------------------------
// PTX helpers (plain sm_80+ features only — target is compute_103, no 'a')
// ---------------------------------------------------------------------------
__device__ __forceinline__ uint32_t smem_u32(const void* p) {
    uint32_t a;
    asm("{ .reg .u64 t; cvta.to.shared.u64 t, %1; cvt.u32.u64 %0, t; }" : "=r"(a) : "l"(p));
    return a;
}
__device__ __forceinline__ uint32_t sw128(uint32_t off) { return off ^ ((off >> 3) & 0x70); }

#define LDSM4(r, addr) \
    asm volatile("ldmatrix.sync.aligned.m8n8.x4.shared.b16 {%0,%1,%2,%3}, [%4];" \
        : "=r"((r)[0]), "=r"((r)[1]), "=r"((r)[2]), "=r"((r)[3]) : "r"(addr))

#define MMA(c, a, b) \
    asm volatile("mma.sync.aligned.m16n8k16.row.col.f32.f16.f16.f32 " \
        "{%0,%1,%2,%3}, {%4,%5,%6,%7}, {%8,%9}, {%0,%1,%2,%3};" \
        : "+f"((c)[0]), "+f"((c)[1]), "+f"((c)[2]), "+f"((c)[3]) \
        : "r"((a)[0]), "r"((a)[1]), "r"((a)[2]), "r"((a)[3]), "r"((b)[0]), "r"((b)[1]))

#define CP16(dst, src) \
    asm volatile("cp.async.cg.shared.global [%0], [%1], 16;" :: "r"(dst), "l"(src) : "memory")
#define CP_COMMIT() asm volatile("cp.async.commit_group;" ::: "memory")
#define CP_WAIT0()  asm volatile("cp.async.wait_group 0;" ::: "memory")

// ---------------------------------------------------------------------------
// Prep: Wm fp32 [1024][512] -> transposed fp16 g_bh [512][1024] via 32x32
// smem tiles (both gmem sides coalesced). Blocks 0..511 transpose; blocks
// 512..519 run the backward min-scan of u.
// ---------------------------------------------------------------------------
__global__ void prep_kernel(const float* __restrict__ Wm, const int* __restrict__ u)
{
    if (blockIdx.x < TP_BLKS) {
        __shared__ __half tile[32][33];
        const int n0 = (blockIdx.x & 15) * 32;       // Hd/32 = 16
        const int k0 = (blockIdx.x >> 4) * 32;
        const int tx = threadIdx.x & 31;
        const int ty = threadIdx.x >> 5;             // 0..7
        #pragma unroll
        for (int kk = 0; kk < 4; ++kk) {
            const int kl = ty + kk * 8;
            tile[kl][tx] = __float2half_rn(Wm[(size_t)(k0 + kl) * Hd + n0 + tx]);
        }
        __syncthreads();
        #pragma unroll
        for (int kk = 0; kk < 4; ++kk) {
            const int nl = ty + kk * 8;
            g_bh[(size_t)(n0 + nl) * K2 + k0 + tx] = __half_as_ushort(tile[tx][nl]);
        }
        return;
    }
    // ---- scan part ----
    __shared__ int sv[Td];
    const int b = blockIdx.x - TP_BLKS;
    for (int t = threadIdx.x; t < Td; t += blockDim.x)
        sv[t] = (u[(size_t)b * Td + t] > 0) ? t : Td;
    __syncthreads();
    for (int off = 1; off < Td; off <<= 1) {
        int tmp[Td / 256];
        #pragma unroll
        for (int i = 0; i < Td / 256; ++i) {
            const int t = threadIdx.x + i * 256;
            int v = sv[t];
            if (t + off < Td) v = min(v, sv[t + off]);
            tmp[i] = v;
        }
        __syncthreads();
        #pragma unroll
        for (int i = 0; i < Td / 256; ++i)
            sv[threadIdx.x + i * 256] = tmp[i];
        __syncthreads();
    }
    for (int t = threadIdx.x; t < Td; t += blockDim.x) {
        const int n = sv[t];
        g_idx[(size_t)b * Td + t] = (n < Td) ? n : t;
    }
}

// ---------------------------------------------------------------------------
// GEMM building blocks (kc64 = 64-wide K sub-chunk index, 0..15)
// ---------------------------------------------------------------------------
__device__ __forceinline__ void load_a_regs(const float* __restrict__ senders,
                                            size_t m0, int kc64, int tid, float4 (&va)[8])
{
    #pragma unroll
    for (int j = 0; j < 8; ++j) {
        const int i = tid + j * NTHREADS;
        const int row = i >> 4, c = i & 15;
        va[j] = ((const float4*)(senders + (m0 + row) * K2 + kc64 * 64))[c];
    }
}

__device__ __forceinline__ void cp_b_sub(uint32_t dstSub, int n0, int kc64, int tid)
{
    #pragma unroll
    for (int j = 0; j < 8; ++j) {
        const int i = tid + j * NTHREADS;      // 0..2047
        const int row = i >> 3, u = i & 7;     // row 0..255
        const char* gh = (const char*)(g_bh + (size_t)(n0 + row) * K2 + kc64 * 64) + u * 16;
        const uint32_t swo = sw128(row * 128 + u * 16);
        CP16(dstSub + swo, gh);
    }
}

__device__ __forceinline__ void convert_store_a(const float4 (&va)[8], char* dstSub, int tid)
{
    #pragma unroll
    for (int j = 0; j < 8; ++j) {
        const int i = tid + j * NTHREADS;
        const int row = i >> 4, c = i & 15;
        const float4 v = va[j];
        uint32_t p0, p1;
        asm("cvt.rn.f16x2.f32 %0, %1, %2;" : "=r"(p0) : "f"(v.y), "f"(v.x));
        asm("cvt.rn.f16x2.f32 %0, %1, %2;" : "=r"(p1) : "f"(v.w), "f"(v.z));
        const uint32_t swo = sw128(row * 128 + c * 8);
        *(uint2*)(dstSub + swo) = make_uint2(p0, p1);
    }
}

__device__ __forceinline__ void compute_k16(uint32_t aBase, uint32_t bBase, int kk,
                                            int lane, int wm, int wn, float (&acc)[4][8][4])
{
    uint32_t af[4][4], bf[4][4];
    const int koffA = kk * 32 + ((lane >> 4) << 4);
    const int arow = wm * 64 + (lane & 15);
    #pragma unroll
    for (int mt = 0; mt < 4; ++mt)
        LDSM4(af[mt], aBase + sw128((arow + mt * 16) * 128 + koffA));
    const int nrow = wn * 64 + (lane & 7) + ((lane & 16) ? 8 : 0);
    const int koffB = kk * 32 + ((lane >> 3) & 1) * 16;
    #pragma unroll
    for (int h = 0; h < 4; ++h)
        LDSM4(bf[h], bBase + sw128((nrow + h * 16) * 128 + koffB));

    #pragma unroll
    for (int mt = 0; mt < 4; ++mt)
        #pragma unroll
        for (int nt = 0; nt < 8; ++nt)
            MMA(acc[mt][nt], af[mt], (&bf[nt >> 1][(nt & 1) * 2]));
}

// ---------------------------------------------------------------------------
// fp16 GEMM via mma.sync (fp32 accum): g_msg = fp16(senders @ Wm)
// gridDim = (2 n-tiles, 896 m-tiles); 256 thr; warp grid 2(M)x4(N), 64x64 each
// K=128 per barrier period (two 64-wide sub-tiles), 2-stage double buffer.
// ---------------------------------------------------------------------------
__global__ void __launch_bounds__(NTHREADS, 1)
gemm_kernel(const float* __restrict__ senders)
{
    extern __shared__ __align__(128) char smem[];
    const uint32_t sb = smem_u32(smem);
    const int tid = threadIdx.x, lane = tid & 31, wid = tid >> 5;
    const int wm = wid >> 2, wn = wid & 3;
    const int n0 = blockIdx.x * NTILE;
    const size_t m0 = (size_t)blockIdx.y * MT;

    float acc[4][8][4];
    #pragma unroll
    for (int i = 0; i < 4; ++i)
        #pragma unroll
        for (int j = 0; j < 8; ++j)
            #pragma unroll
            for (int q = 0; q < 4; ++q) acc[i][j][q] = 0.f;

    float4 va[8];

    // ---- prologue: fill stage 0 (both sub-tiles) ----
    {
        cp_b_sub(sb + OFF_B0, n0, 0, tid);
        cp_b_sub(sb + OFF_B1, n0, 1, tid);
        CP_COMMIT();
        load_a_regs(senders, m0, 0, tid, va);
        convert_store_a(va, smem + OFF_A0, tid);
        load_a_regs(senders, m0, 1, tid, va);
        convert_store_a(va, smem + OFF_A1, tid);
        CP_WAIT0();
        __syncthreads();
    }

    // ---- main loop: one barrier period per K=128 ----
    for (int kc2 = 0; kc2 < NCHUNK2; ++kc2) {
        const int st = kc2 & 1;
        const uint32_t sg = sb + st * STG;
        char* nxt = smem + (st ^ 1) * STG;
        const uint32_t nxtu = sb + (st ^ 1) * STG;
        const bool more = (kc2 + 1 < NCHUNK2);

        if (more) {
            cp_b_sub(nxtu + OFF_B0, n0, 2 * kc2 + 2, tid);
            cp_b_sub(nxtu + OFF_B1, n0, 2 * kc2 + 3, tid);
            CP_COMMIT();
            load_a_regs(senders, m0, 2 * kc2 + 2, tid, va);  // half0 LDG in flight
        }

        compute_k16(sg + OFF_A0, sg + OFF_B0, 0, lane, wm, wn, acc);
        compute_k16(sg + OFF_A0, sg + OFF_B0, 1, lane, wm, wn, acc);

        if (more) convert_store_a(va, nxt + OFF_A0, tid);

        compute_k16(sg + OFF_A0, sg + OFF_B0, 2, lane, wm, wn, acc);
        compute_k16(sg + OFF_A0, sg + OFF_B0, 3, lane, wm, wn, acc);

        if (more) load_a_regs(senders, m0, 2 * kc2 + 3, tid, va);  // half1 LDG in flight

        compute_k16(sg + OFF_A1, sg + OFF_B1, 0, lane, wm, wn, acc);
        compute_k16(sg + OFF_A1, sg + OFF_B1, 1, lane, wm, wn, acc);

        if (more) convert_store_a(va, nxt + OFF_A1, tid);

        compute_k16(sg + OFF_A1, sg + OFF_B1, 2, lane, wm, wn, acc);
        compute_k16(sg + OFF_A1, sg + OFF_B1, 3, lane, wm, wn, acc);

        if (more) CP_WAIT0();
        __syncthreads();
    }

    // ---- epilogue: write fp16 GEMM result ----
    const int g = lane >> 2, tg = lane & 3;
    #pragma unroll
    for (int mt = 0; mt < 4; ++mt) {
        #pragma unroll
        for (int nt = 0; nt < 8; ++nt) {
            const size_t row = m0 + wm * 64 + mt * 16 + g;
            const int col = n0 + wn * 64 + nt * 8 + tg * 2;
            __half2* p = g_msg + (row * Hd + col) / 2;
            p[0]          = __floats2half2_rn(acc[mt][nt][0], acc[mt][nt][1]);
            p[8 * Hd / 2] = __floats2half2_rn(acc[mt][nt][2], acc[mt][nt][3]);
        }
    }
}

// ---------------------------------------------------------------------------
// Attention + hx gather: per (b,t) -> bias+relu+mask, masked softmax over S=7,
// aggregate; also copies hx_s[b, idx[bt]] into out[..., H:2H].
// ---------------------------------------------------------------------------
__global__ void __launch_bounds__(128)
attn_kernel(const float* __restrict__ query,
            const float* __restrict__ smask,
            const float* __restrict__ bm,
            const float* __restrict__ hx,
            float* __restrict__ out)
{
    __shared__ float red[4][Sd];
    __shared__ float s_att[Sd];
    const int bt = blockIdx.x;
    const int tid = threadIdx.x;
    const int lane = tid & 31, wid = tid >> 5;

    // ---- hx gather half (independent of attention math) ----
    {
        const int b = bt >> 11;                         // T = 2048
        const int idx = g_idx[bt];
        const float4 v = ((const float4*)(hx + ((size_t)(b * Td + idx)) * Hd))[tid];
        ((float4*)(out + (size_t)bt * (2 * Hd) + Hd))[tid] = v;
    }

    const float4 q   = ((const float4*)(query + (size_t)bt * Hd))[tid];
    const float4 bmv = ((const float4*)bm)[tid];
    float msk[Sd];
    #pragma unroll
    for (int s = 0; s < Sd; ++s) msk[s] = smask[(size_t)bt * Sd + s];

    float4 m[Sd];
    float lg[Sd];
    #pragma unroll
    for (int s = 0; s < Sd; ++s) {
        const uint2 raw = *(const uint2*)(g_msg + ((size_t)bt * Sd + s) * Hd / 2 + tid * 2);
        const float2 f0 = __half22float2(*(const __half2*)&raw.x);
        const float2 f1 = __half22float2(*(const __half2*)&raw.y);
        float4 mv;
        mv.x = fmaxf(f0.x + bmv.x, 0.f) * msk[s];
        mv.y = fmaxf(f0.y + bmv.y, 0.f) * msk[s];
        mv.z = fmaxf(f1.x + bmv.z, 0.f) * msk[s];
        mv.w = fmaxf(f1.y + bmv.w, 0.f) * msk[s];
        m[s] = mv;
        float v = q.x * mv.x + q.y * mv.y + q.z * mv.z + q.w * mv.w;
        v += __shfl_xor_sync(0xffffffffu, v, 16);
        v += __shfl_xor_sync(0xffffffffu, v, 8);
        v += __shfl_xor_sync(0xffffffffu, v, 4);
        v += __shfl_xor_sync(0xffffffffu, v, 2);
        v += __shfl_xor_sync(0xffffffffu, v, 1);
        lg[s] = v;
    }
    if (lane == 0) {
        #pragma unroll
        for (int s = 0; s < Sd; ++s) red[wid][s] = lg[s];
    }
    __syncthreads();
    if (tid == 0) {
        float l[Sd], maxv = -3.0e38f;
        int any = 0;
        #pragma unroll
        for (int s = 0; s < Sd; ++s) {
            l[s] = (red[0][s] + red[1][s] + red[2][s] + red[3][s]) * 0.044194173824159216f;
            if (msk[s] > 0.f) { any = 1; if (l[s] > maxv) maxv = l[s]; }
        }
        float sum = 0.f, e[Sd];
        #pragma unroll
        for (int s = 0; s < Sd; ++s) {
            e[s] = (msk[s] > 0.f) ? expf(l[s] - maxv) : 0.f;
            sum += e[s];
        }
        const float inv = (any && sum > 0.f) ? (1.f / sum) : 0.f;
        #pragma unroll
        for (int s = 0; s < Sd; ++s) s_att[s] = e[s] * inv;
    }
    __syncthreads();

    float4 a = make_float4(0.f, 0.f, 0.f, 0.f);
    #pragma unroll
    for (int s = 0; s < Sd; ++s) {
        const float w = s_att[s];
        a.x = fmaf(w, m[s].x, a.x);
        a.y = fmaf(w, m[s].y, a.y);
        a.z = fmaf(w, m[s].z, a.z);
        a.w = fmaf(w, m[s].w, a.w);
    }
    ((float4*)(out + (size_t)bt * (2 * Hd)))[tid] = a;
}

// ---------------------------------------------------------------------------
extern "C" void kernel_launch(void* const* d_in, const int* in_sizes, int n_in,
                              void* d_out, int out_size)
{
    const float* query   = (const float*)d_in[0];
    const float* senders = (const float*)d_in[1];
    const float* smaskp  = (const float*)d_in[2];
    const float* Wm      = (const float*)d_in[3];
    const float* bm      = (const float*)d_in[4];
    const float* hx      = (const float*)d_in[5];
    const int*   u       = (const int*)d_in[6];
    float* out = (float*)d_out;

    cudaFuncSetAttribute(gemm_kernel,
                         cudaFuncAttributeMaxDynamicSharedMemorySize, GEMM_SMEM);

    prep_kernel<<<TP_BLKS + Bd, 256>>>(Wm, u);
    gemm_kernel<<<dim3(2, MROWS / MT), NTHREADS, GEMM_SMEM>>>(senders);
    attn_kernel<<<Bd * Td, 128>>>(query, smaskp, bm, hx, out);
}

// round 16
// speedup vs baseline: 1.0540x; 1.0107x over previous
#include <cuda_runtime.h>
#include <cuda_fp16.h>
#include <math.h>
#include <stdint.h>

#define Bd 8
#define Td 2048
#define Sd 7
#define Hd 512
#define K2 1024                 // GEMM K
#define MROWS (Bd*Td*Sd)        // 114688

#define MT 128                  // CTA M tile
#define NTILE 256               // CTA N tile
#define NCHUNK2 8               // K=128 per barrier period
#define NTHREADS 256

// smem stage layout (bytes): two 64-wide sub-tiles each for A and B
#define OFF_A0 0
#define OFF_A1 16384
#define OFF_B0 32768
#define OFF_B1 65536
#define STG    98304
#define GEMM_SMEM (2*STG)       // 196608

// prep transpose tiling: 32x32 fp32->fp16 tiles
#define TP_BLKS ((Hd/32)*(K2/32))   // 512

// ---------------------------------------------------------------------------
// Device scratch (no cudaMalloc allowed)
// ---------------------------------------------------------------------------
__device__ __half2 g_msg[(size_t)MROWS * Hd / 2]; // GEMM output (pre bias/relu), fp16
__device__ unsigned short g_bh[Hd * K2];          // Wm^T fp16 [N=512][K=1024]
__device__ int g_idx[Bd * Td];

// ---------------------------------------------------------------------------
// PTX helpers (plain sm_80+ features only — target is compute_103, no 'a')
// ---------------------------------------------------------------------------
__device__ __forceinline__ uint32_t smem_u32(const void* p) {
    uint32_t a;
    asm("{ .reg .u64 t; cvta.to.shared.u64 t, %1; cvt.u32.u64 %0, t; }" : "=r"(a) : "l"(p));
    return a;
}
__device__ __forceinline__ uint32_t sw128(uint32_t off) { return off ^ ((off >> 3) & 0x70); }

#define LDSM4(r, addr) \
    asm volatile("ldmatrix.sync.aligned.m8n8.x4.shared.b16 {%0,%1,%2,%3}, [%4];" \
        : "=r"((r)[0]), "=r"((r)[1]), "=r"((r)[2]), "=r"((r)[3]) : "r"(addr))

#define MMA(c, a, b) \
    asm volatile("mma.sync.aligned.m16n8k16.row.col.f32.f16.f16.f32 " \
        "{%0,%1,%2,%3}, {%4,%5,%6,%7}, {%8,%9}, {%0,%1,%2,%3};" \
        : "+f"((c)[0]), "+f"((c)[1]), "+f"((c)[2]), "+f"((c)[3]) \
        : "r"((a)[0]), "r"((a)[1]), "r"((a)[2]), "r"((a)[3]), "r"((b)[0]), "r"((b)[1]))

#define CP16(dst, src) \
    asm volatile("cp.async.cg.shared.global [%0], [%1], 16;" :: "r"(dst), "l"(src) : "memory")
#define CP_COMMIT() asm volatile("cp.async.commit_group;" ::: "memory")
#define CP_WAIT0()  asm volatile("cp.async.wait_group 0;" ::: "memory")

// ---------------------------------------------------------------------------
// Prep: Wm fp32 [1024][512] -> transposed fp16 g_bh [512][1024] via 32x32
// smem tiles; blocks 512..519 run the backward min-scan of u.
// ---------------------------------------------------------------------------
__global__ void prep_kernel(const float* __restrict__ Wm, const int* __restrict__ u)
{
    if (blockIdx.x < TP_BLKS) {
        __shared__ __half tile[32][33];
        const int n0 = (blockIdx.x & 15) * 32;
        const int k0 = (blockIdx.x >> 4) * 32;
        const int tx = threadIdx.x & 31;
        const int ty = threadIdx.x >> 5;
        #pragma unroll
        for (int kk = 0; kk < 4; ++kk) {
            const int kl = ty + kk * 8;
            tile[kl][tx] = __float2half_rn(Wm[(size_t)(k0 + kl) * Hd + n0 + tx]);
        }
        __syncthreads();
        #pragma unroll
        for (int kk = 0; kk < 4; ++kk) {
            const int nl = ty + kk * 8;
            g_bh[(size_t)(n0 + nl) * K2 + k0 + tx] = __half_as_ushort(tile[tx][nl]);
        }
        return;
    }
    __shared__ int sv[Td];
    const int b = blockIdx.x - TP_BLKS;
    for (int t = threadIdx.x; t < Td; t += blockDim.x)
        sv[t] = (u[(size_t)b * Td + t] > 0) ? t : Td;
    __syncthreads();
    for (int off = 1; off < Td; off <<= 1) {
        int tmp[Td / 256];
        #pragma unroll
        for (int i = 0; i < Td / 256; ++i) {
            const int t = threadIdx.x + i * 256;
            int v = sv[t];
            if (t + off < Td) v = min(v, sv[t + off]);
            tmp[i] = v;
        }
        __syncthreads();
        #pragma unroll
        for (int i = 0; i < Td / 256; ++i)
            sv[threadIdx.x + i * 256] = tmp[i];
        __syncthreads();
    }
    for (int t = threadIdx.x; t < Td; t += blockDim.x) {
        const int n = sv[t];
        g_idx[(size_t)b * Td + t] = (n < Td) ? n : t;
    }
}

// ---------------------------------------------------------------------------
// GEMM building blocks (kc64 = 64-wide K sub-chunk index, 0..15)
// ---------------------------------------------------------------------------
__device__ __forceinline__ void load_a_regs(const float* __restrict__ senders,
                                            size_t m0, int kc64, int tid, float4 (&va)[8])
{
    #pragma unroll
    for (int j = 0; j < 8; ++j) {
        const int i = tid + j * NTHREADS;
        const int row = i >> 4, c = i & 15;
        va[j] = ((const float4*)(senders + (m0 + row) * K2 + kc64 * 64))[c];
    }
}

__device__ __forceinline__ void cp_b_sub(uint32_t dstSub, int n0, int kc64, int tid)
{
    #pragma unroll
    for (int j = 0; j < 8; ++j) {
        const int i = tid + j * NTHREADS;
        const int row = i >> 3, u = i & 7;
        const char* gh = (const char*)(g_bh + (size_t)(n0 + row) * K2 + kc64 * 64) + u * 16;
        const uint32_t swo = sw128(row * 128 + u * 16);
        CP16(dstSub + swo, gh);
    }
}

__device__ __forceinline__ void convert_store_a(const float4 (&va)[8], char* dstSub, int tid)
{
    #pragma unroll
    for (int j = 0; j < 8; ++j) {
        const int i = tid + j * NTHREADS;
        const int row = i >> 4, c = i & 15;
        const float4 v = va[j];
        uint32_t p0, p1;
        asm("cvt.rn.f16x2.f32 %0, %1, %2;" : "=r"(p0) : "f"(v.y), "f"(v.x));
        asm("cvt.rn.f16x2.f32 %0, %1, %2;" : "=r"(p1) : "f"(v.w), "f"(v.z));
        const uint32_t swo = sw128(row * 128 + c * 8);
        *(uint2*)(dstSub + swo) = make_uint2(p0, p1);
    }
}

__device__ __forceinline__ void compute_k16(uint32_t aBase, uint32_t bBase, int kk,
                                            int lane, int wm, int wn, float (&acc)[4][8][4])
{
    uint32_t af[4][4], bf[4][4];
    const int koffA = kk * 32 + ((lane >> 4) << 4);
    const int arow = wm * 64 + (lane & 15);
    #pragma unroll
    for (int mt = 0; mt < 4; ++mt)
        LDSM4(af[mt], aBase + sw128((arow + mt * 16) * 128 + koffA));
    const int nrow = wn * 64 + (lane & 7) + ((lane & 16) ? 8 : 0);
    const int koffB = kk * 32 + ((lane >> 3) & 1) * 16;
    #pragma unroll
    for (int h = 0; h < 4; ++h)
        LDSM4(bf[h], bBase + sw128((nrow + h * 16) * 128 + koffB));

    #pragma unroll
    for (int mt = 0; mt < 4; ++mt)
        #pragma unroll
        for (int nt = 0; nt < 8; ++nt)
            MMA(acc[mt][nt], af[mt], (&bf[nt >> 1][(nt & 1) * 2]));
}

// ---------------------------------------------------------------------------
// fp16 GEMM via mma.sync (fp32 accum): g_msg = fp16(senders @ Wm)
// gridDim = (2 n-tiles, 896 m-tiles); 256 thr; warp grid 2(M)x4(N), 64x64 each
// K=128 per barrier period (two 64-wide sub-tiles), 2-stage double buffer.
// ---------------------------------------------------------------------------
__global__ void __launch_bounds__(NTHREADS, 1)
gemm_kernel(const float* __restrict__ senders)
{
    extern __shared__ __align__(128) char smem[];
    const uint32_t sb = smem_u32(smem);
    const int tid = threadIdx.x, lane = tid & 31, wid = tid >> 5;
    const int wm = wid >> 2, wn = wid & 3;
    const int n0 = blockIdx.x * NTILE;
    const size_t m0 = (size_t)blockIdx.y * MT;

    float acc[4][8][4];
    #pragma unroll
    for (int i = 0; i < 4; ++i)
        #pragma unroll
        for (int j = 0; j < 8; ++j)
            #pragma unroll
            for (int q = 0; q < 4; ++q) acc[i][j][q] = 0.f;

    float4 va[8];

    // ---- prologue: fill stage 0 (both sub-tiles) ----
    {
        cp_b_sub(sb + OFF_B0, n0, 0, tid);
        cp_b_sub(sb + OFF_B1, n0, 1, tid);
        CP_COMMIT();
        load_a_regs(senders, m0, 0, tid, va);
        convert_store_a(va, smem + OFF_A0, tid);
        load_a_regs(senders, m0, 1, tid, va);
        convert_store_a(va, smem + OFF_A1, tid);
        CP_WAIT0();
        __syncthreads();
    }

    // ---- main loop: one barrier period per K=128 ----
    for (int kc2 = 0; kc2 < NCHUNK2; ++kc2) {
        const int st = kc2 & 1;
        const uint32_t sg = sb + st * STG;
        char* nxt = smem + (st ^ 1) * STG;
        const uint32_t nxtu = sb + (st ^ 1) * STG;
        const bool more = (kc2 + 1 < NCHUNK2);

        if (more) {
            cp_b_sub(nxtu + OFF_B0, n0, 2 * kc2 + 2, tid);
            cp_b_sub(nxtu + OFF_B1, n0, 2 * kc2 + 3, tid);
            CP_COMMIT();
            load_a_regs(senders, m0, 2 * kc2 + 2, tid, va);  // half0 LDG in flight
        }

        compute_k16(sg + OFF_A0, sg + OFF_B0, 0, lane, wm, wn, acc);
        compute_k16(sg + OFF_A0, sg + OFF_B0, 1, lane, wm, wn, acc);

        if (more) convert_store_a(va, nxt + OFF_A0, tid);

        compute_k16(sg + OFF_A0, sg + OFF_B0, 2, lane, wm, wn, acc);
        compute_k16(sg + OFF_A0, sg + OFF_B0, 3, lane, wm, wn, acc);

        if (more) load_a_regs(senders, m0, 2 * kc2 + 3, tid, va);  // half1 LDG in flight

        compute_k16(sg + OFF_A1, sg + OFF_B1, 0, lane, wm, wn, acc);
        compute_k16(sg + OFF_A1, sg + OFF_B1, 1, lane, wm, wn, acc);

        if (more) convert_store_a(va, nxt + OFF_A1, tid);

        compute_k16(sg + OFF_A1, sg + OFF_B1, 2, lane, wm, wn, acc);
        compute_k16(sg + OFF_A1, sg + OFF_B1, 3, lane, wm, wn, acc);

        if (more) CP_WAIT0();
        __syncthreads();
    }

    // ---- epilogue: write fp16 GEMM result ----
    const int g = lane >> 2, tg = lane & 3;
    #pragma unroll
    for (int mt = 0; mt < 4; ++mt) {
        #pragma unroll
        for (int nt = 0; nt < 8; ++nt) {
            const size_t row = m0 + wm * 64 + mt * 16 + g;
            const int col = n0 + wn * 64 + nt * 8 + tg * 2;
            __half2* p = g_msg + (row * Hd + col) / 2;
            p[0]          = __floats2half2_rn(acc[mt][nt][0], acc[mt][nt][1]);
            p[8 * Hd / 2] = __floats2half2_rn(acc[mt][nt][2], acc[mt][nt][3]);
        }
    }
}

// ---------------------------------------------------------------------------
// Attention + hx gather: per (b,t) -> bias+relu+mask, masked softmax over S=7,
// aggregate; also copies hx_s[b, idx[bt]] into out[..., H:2H].
// Shuffle reduction is level-major across s for ILP (7 independent shuffles
// per level instead of a 5-deep dependent chain per s).
// ---------------------------------------------------------------------------
__global__ void __launch_bounds__(128)
attn_kernel(const float* __restrict__ query,
            const float* __restrict__ smask,
            const float* __restrict__ bm,
            const float* __restrict__ hx,
            float* __restrict__ out)
{
    __shared__ float red[4][Sd];
    __shared__ float s_att[Sd];
    const int bt = blockIdx.x;
    const int tid = threadIdx.x;
    const int lane = tid & 31, wid = tid >> 5;

    // ---- hx gather half (independent of attention math) ----
    {
        const int b = bt >> 11;                         // T = 2048
        const int idx = g_idx[bt];
        const float4 v = ((const float4*)(hx + ((size_t)(b * Td + idx)) * Hd))[tid];
        ((float4*)(out + (size_t)bt * (2 * Hd) + Hd))[tid] = v;
    }

    const float4 q   = ((const float4*)(query + (size_t)bt * Hd))[tid];
    const float4 bmv = ((const float4*)bm)[tid];
    float msk[Sd];
    #pragma unroll
    for (int s = 0; s < Sd; ++s) msk[s] = smask[(size_t)bt * Sd + s];

    float4 m[Sd];
    float lg[Sd];
    #pragma unroll
    for (int s = 0; s < Sd; ++s) {
        const uint2 raw = *(const uint2*)(g_msg + ((size_t)bt * Sd + s) * Hd / 2 + tid * 2);
        const float2 f0 = __half22float2(*(const __half2*)&raw.x);
        const float2 f1 = __half22float2(*(const __half2*)&raw.y);
        float4 mv;
        mv.x = fmaxf(f0.x + bmv.x, 0.f) * msk[s];
        mv.y = fmaxf(f0.y + bmv.y, 0.f) * msk[s];
        mv.z = fmaxf(f1.x + bmv.z, 0.f) * msk[s];
        mv.w = fmaxf(f1.y + bmv.w, 0.f) * msk[s];
        m[s] = mv;
        lg[s] = q.x * mv.x + q.y * mv.y + q.z * mv.z + q.w * mv.w;
    }
    // level-major butterfly: shuffles within a level are independent (ILP)
    #pragma unroll
    for (int off = 16; off >= 1; off >>= 1) {
        #pragma unroll
        for (int s = 0; s < Sd; ++s)
            lg[s] += __shfl_xor_sync(0xffffffffu, lg[s], off);
    }
    if (lane == 0) {
        #pragma unroll
        for (int s = 0; s < Sd; ++s) red[wid][s] = lg[s];
    }
    __syncthreads();
    if (tid == 0) {
        float l[Sd], maxv = -3.0e38f;
        int any = 0;
        #pragma unroll
        for (int s = 0; s < Sd; ++s) {
            l[s] = (red[0][s] + red[1][s] + red[2][s] + red[3][s]) * 0.044194173824159216f;
            if (msk[s] > 0.f) { any = 1; if (l[s] > maxv) maxv = l[s]; }
        }
        float sum = 0.f, e[Sd];
        #pragma unroll
        for (int s = 0; s < Sd; ++s) {
            e[s] = (msk[s] > 0.f) ? expf(l[s] - maxv) : 0.f;
            sum += e[s];
        }
        const float inv = (any && sum > 0.f) ? (1.f / sum) : 0.f;
        #pragma unroll
        for (int s = 0; s < Sd; ++s) s_att[s] = e[s] * inv;
    }
    __syncthreads();

    float4 a = make_float4(0.f, 0.f, 0.f, 0.f);
    #pragma unroll
    for (int s = 0; s < Sd; ++s) {
        const float w = s_att[s];
        a.x = fmaf(w, m[s].x, a.x);
        a.y = fmaf(w, m[s].y, a.y);
        a.z = fmaf(w, m[s].z, a.z);
        a.w = fmaf(w, m[s].w, a.w);
    }
    ((float4*)(out + (size_t)bt * (2 * Hd)))[tid] = a;
}

// ---------------------------------------------------------------------------
extern "C" void kernel_launch(void* const* d_in, const int* in_sizes, int n_in,
                              void* d_out, int out_size)
{
    const float* query   = (const float*)d_in[0];
    const float* senders = (const float*)d_in[1];
    const float* smaskp  = (const float*)d_in[2];
    const float* Wm      = (const float*)d_in[3];
    const float* bm      = (const float*)d_in[4];
    const float* hx      = (const float*)d_in[5];
    const int*   u       = (const int*)d_in[6];
    float* out = (float*)d_out;

    cudaFuncSetAttribute(gemm_kernel,
                         cudaFuncAttributeMaxDynamicSharedMemorySize, GEMM_SMEM);

    prep_kernel<<<TP_BLKS + Bd, 256>>>(Wm, u);
    gemm_kernel<<<dim3(2, MROWS / MT), NTHREADS, GEMM_SMEM>>>(senders);
    attn_kernel<<<Bd * Td, 128>>>(query, smaskp, bm, hx, out);
}